// round 9
// baseline (speedup 1.0000x reference)
#include <cuda_runtime.h>

// Fixed problem shape
#define NPIX 102400            // B*H*W = 4*160*160
#define HW   25600
#define NV   1024

// Gaussian in bin coordinates: t = (x+1)*16 - 0.5, sigma_bins = 0.8
// log2-space coefficient: -0.5/(0.8^2) * log2(e)
#define CEXP (-1.12710546f)

__device__ int    g_sizes[NV];
__device__ int    g_start[NV];
__device__ int    g_cursor[NV];
__device__ float4 g_vals[NPIX];     // (t0,t1,t2,t3) per pixel, grouped by segment

// ---------------------------------------------------------------------------
// 1) zero counters
// ---------------------------------------------------------------------------
__global__ void init_kernel() { g_sizes[threadIdx.x] = 0; }

// ---------------------------------------------------------------------------
// 2) segment bincount
// ---------------------------------------------------------------------------
__global__ void count_kernel(const int* __restrict__ seg) {
    int n = blockIdx.x * blockDim.x + threadIdx.x;
    if (n < NPIX) atomicAdd(&g_sizes[seg[n]], 1);
}

// ---------------------------------------------------------------------------
// 3) exclusive scan over 1024 counts (single block, Hillis-Steele)
// ---------------------------------------------------------------------------
__global__ void scan_kernel() {
    __shared__ int s[NV];
    int t = threadIdx.x;
    int x = g_sizes[t];
    s[t] = x;
    __syncthreads();
#pragma unroll
    for (int off = 1; off < NV; off <<= 1) {
        int v = (t >= off) ? s[t - off] : 0;
        __syncthreads();
        s[t] += v;
        __syncthreads();
    }
    int st = s[t] - x;
    g_start[t]  = st;
    g_cursor[t] = st;
}

// ---------------------------------------------------------------------------
// 4) compute per-pixel bin coords and scatter into segment-grouped array
// ---------------------------------------------------------------------------
__global__ void build_kernel(const int* __restrict__ seg,
                             const int* __restrict__ byx,
                             const float* __restrict__ grad) {
    int n = blockIdx.x * blockDim.x + threadIdx.x;
    if (n >= NPIX) return;
    int v = seg[n];
    float t0 = (float)byx[NPIX + n]     * 0.2f - 0.5f;
    float t1 = (float)byx[2 * NPIX + n] * 0.2f - 0.5f;
    int b  = n / HW;
    int hw = n - b * HW;
    float t2 = grad[b * 2 * HW + hw]      * 16.f + 15.5f;
    float t3 = grad[b * 2 * HW + HW + hw] * 16.f + 15.5f;
    int pos = atomicAdd(&g_cursor[v], 1);
    g_vals[pos] = make_float4(t0, t1, t2, t3);
}

// ---------------------------------------------------------------------------
// 5) gather: one block per segment. 4 warps = 2 pairs x 2 pixel-halves.
//    Each warp owns a private 32x33 smem histogram; lane = q column
//    -> conflict-free LDS/FFMA/STS, NO atomics. q dimension is exact
//    (all 32 columns), p window = 6 rows (floor-2..floor+3).
//    Final write covers every output element -> no zero kernel needed,
//    normalization (1/size) folded into the write.
// ---------------------------------------------------------------------------
__global__ void __launch_bounds__(128)
gather_kernel(float* __restrict__ out) {
    __shared__ float H[4][1056];            // 4 x 32 rows x 33 (pad) floats
    int v    = blockIdx.x;
    int tid  = threadIdx.x;
    int wid  = tid >> 5;
    int lane = tid & 31;
    int pr   = wid >> 1;                    // pair 0/1
    int h    = wid & 1;                     // pixel-half 0/1

    int start = g_start[v];
    int cnt   = g_sizes[v];

    float* Hm = H[wid];
#pragma unroll
    for (int k = lane; k < 1056; k += 32) Hm[k] = 0.f;
    // warp-private accumulation: no block sync needed until merge

    float flane = (float)lane;
    for (int i = h; i < cnt; i += 2) {
        float4 tv = g_vals[start + i];      // broadcast load (uniform addr)
        float tp = pr ? tv.z : tv.x;
        float tq = pr ? tv.w : tv.y;
        if (pr && !(tp > -3.5f && tp < 34.5f && tq > -3.5f && tq < 34.5f))
            continue;                       // uniform branch (no divergence)

        float uq = tq - flane;
        float wq = exp2f(CEXP * uq * uq);   // this lane's column weight (exact)
        float ur = tp - flane;
        float wr = exp2f(CEXP * ur * ur);   // row weights, lane r holds row r
        int lo = min(26, max(0, __float2int_rd(tp) - 2));
#pragma unroll
        for (int p = 0; p < 6; p++) {
            float wp = __shfl_sync(0xffffffffu, wr, lo + p);
            Hm[(lo + p) * 33 + lane] += wp * wq;
        }
    }
    __syncthreads();

    float inv = cnt ? 1.0f / (float)cnt : 0.0f;   // den = sizes*(P/32)^2 = sizes
    const float* A = H[pr * 2];
    const float* B = H[pr * 2 + 1];
    float* o = out + (size_t)v * 2048 + pr * 1024;
    int r0 = h * 16;
#pragma unroll
    for (int r = 0; r < 16; r++) {
        int row = r0 + r;
        o[row * 32 + lane] = (A[row * 33 + lane] + B[row * 33 + lane]) * inv;
    }
}

// ---------------------------------------------------------------------------
extern "C" void kernel_launch(void* const* d_in, const int* in_sizes, int n_in,
                              void* d_out, int out_size) {
    const int*   seg  = (const int*)d_in[0];
    const int*   byx  = (const int*)d_in[1];
    const float* grad = (const float*)d_in[2];
    float*       out  = (float*)d_out;

    init_kernel<<<1, NV>>>();
    count_kernel<<<(NPIX + 255) / 256, 256>>>(seg);
    scan_kernel<<<1, NV>>>();
    build_kernel<<<(NPIX + 255) / 256, 256>>>(seg, byx, grad);
    gather_kernel<<<NV, 128>>>(out);
}

// round 10
// speedup vs baseline: 1.6174x; 1.6174x over previous
#include <cuda_runtime.h>
#include <cstdint>

// Fixed problem shape
#define NPIX      102400            // B*H*W = 4*160*160
#define HW        25600             // H*W
#define NV        1024
#define OUT_ELEMS (NV * 2 * 32 * 32)   // 2,097,152 floats = 8 MB

// Gaussian in bin coordinates: t = (x+1)*16 - 0.5, sigma_bins = 0.8
// log2-space coefficient: -0.5/(0.8^2) * log2(e)
#define CEXP   (-1.12710546f)
#define SKIPTH (2e-5f)

__device__ int g_sizes[NV];

// ---------------------------------------------------------------------------
// Kernel 1: zero output via TMA bulk stores (STG.128 dispatch-limited before:
// 524k STG x 12cyc issue; TMA does 8.4MB at ~6300 B/cyc chip-wide ~0.8us).
// 512 blocks x 128 thr; each block stages 16KB of zeros in smem and bulk-
// stores it. g_sizes zeroed here too (count runs in the next kernel).
// ---------------------------------------------------------------------------
__global__ void __launch_bounds__(128) zero_kernel(float* __restrict__ out) {
    __shared__ __align__(16) float buf[4096];           // 16 KB
    float4 z = make_float4(0.f, 0.f, 0.f, 0.f);
#pragma unroll
    for (int k = 0; k < 8; k++)
        reinterpret_cast<float4*>(buf)[threadIdx.x + k * 128] = z;

    int gi = blockIdx.x * 128 + threadIdx.x;
    if (gi < NV) g_sizes[gi] = 0;

    asm volatile("fence.proxy.async;" ::: "memory");
    __syncthreads();

    if (threadIdx.x == 0) {
        uint32_t src;
        asm("{ .reg .u64 t; cvta.to.shared.u64 t, %1; cvt.u32.u64 %0, t; }"
            : "=r"(src) : "l"(buf));
        float* dst = out + (size_t)blockIdx.x * 4096;
        asm volatile(
            "cp.async.bulk.global.shared::cta.bulk_group [%0], [%1], %2;\n\t"
            "cp.async.bulk.commit_group;\n\t"
            "cp.async.bulk.wait_group 0;\n\t"
            :: "l"(dst), "r"(src), "n"(16384) : "memory");
    }
}

// ---------------------------------------------------------------------------
// Kernel 2: segment bincount (ordered after zero_kernel)
// ---------------------------------------------------------------------------
__global__ void count_kernel(const int* __restrict__ seg) {
    int n = blockIdx.x * blockDim.x + threadIdx.x;
    if (n < NPIX) atomicAdd(&g_sizes[seg[n]], 1);
}

// ---------------------------------------------------------------------------
// Predicated vector reduction: issue red.v4 only if gate > SKIPTH.
// ---------------------------------------------------------------------------
__device__ __forceinline__ void red4p(float gate, float* p,
                                      float a, float b, float c, float d) {
    asm volatile(
        "{\n\t"
        ".reg .pred pg;\n\t"
        "setp.gt.f32 pg, %0, %1;\n\t"
        "@pg red.global.add.v4.f32 [%2], {%3,%4,%5,%6};\n\t"
        "}"
        :: "f"(gate), "f"(SKIPTH), "l"(p), "f"(a), "f"(b), "f"(c), "f"(d)
        : "memory");
}

// ---------------------------------------------------------------------------
// Kernel 3: windowed Parzen scatter (R4 structure — measured 17.4us, near the
// REDG per-lane dispatch floor). p-window 6 rows, q-window 12 cols 4-aligned,
// chunks with product weight < SKIPTH predicated off. Normalization folded in.
// ---------------------------------------------------------------------------
__global__ void __launch_bounds__(256)
hist_kernel(const int* __restrict__ seg,
            const int* __restrict__ byx,
            const float* __restrict__ grad,
            float* __restrict__ out) {
    int n = blockIdx.x * blockDim.x + threadIdx.x;
    if (n >= NPIX) return;

    int v = seg[n];
    float inv = 1.0f / (float)__ldg(&g_sizes[v]);   // den = sizes*(P/32)^2 = sizes

    // bin coordinates: t = (x+1)*16 - 0.5
    float t0 = (float)byx[NPIX + n]     * 0.2f - 0.5f;
    float t1 = (float)byx[2 * NPIX + n] * 0.2f - 0.5f;
    int   b  = n / HW;
    int   hw = n - b * HW;
    float t2 = grad[b * 2 * HW + hw]      * 16.f + 15.5f;
    float t3 = grad[b * 2 * HW + HW + hw] * 16.f + 15.5f;

    float* base0 = out + (size_t)v * 2048;

    // ---- pair 0: dims (0,1) — always in range ----
    {
        int lo0 = min(26, max(0, __float2int_rd(t0) - 2));
        float w0[6];
#pragma unroll
        for (int k = 0; k < 6; k++) {
            float d = t0 - (float)(lo0 + k);
            w0[k] = exp2f(CEXP * d * d);
        }
        int qa1 = min(20, max(0, (__float2int_rd(t1) - 3) & ~3));
        float w1[12];
#pragma unroll
        for (int k = 0; k < 12; k++) {
            float d = t1 - (float)(qa1 + k);
            w1[k] = exp2f(CEXP * d * d);
        }
        float m0 = fmaxf(fmaxf(w1[0], w1[1]),  fmaxf(w1[2],  w1[3]));
        float m1 = fmaxf(fmaxf(w1[4], w1[5]),  fmaxf(w1[6],  w1[7]));
        float m2 = fmaxf(fmaxf(w1[8], w1[9]),  fmaxf(w1[10], w1[11]));
#pragma unroll
        for (int p = 0; p < 6; p++) {
            float wr = w0[p];
            float a  = wr * inv;
            float* row = base0 + (lo0 + p) * 32 + qa1;
            red4p(wr * m0, row,     a * w1[0], a * w1[1], a * w1[2],  a * w1[3]);
            red4p(wr * m1, row + 4, a * w1[4], a * w1[5], a * w1[6],  a * w1[7]);
            red4p(wr * m2, row + 8, a * w1[8], a * w1[9], a * w1[10], a * w1[11]);
        }
    }

    // ---- pair 1: dims (2,3) — grads can fall outside all bins -> skip ----
    if (t2 > -3.5f && t2 < 34.5f && t3 > -3.5f && t3 < 34.5f) {
        int lo2 = min(26, max(0, __float2int_rd(t2) - 2));
        float w2[6];
#pragma unroll
        for (int k = 0; k < 6; k++) {
            float d = t2 - (float)(lo2 + k);
            w2[k] = exp2f(CEXP * d * d);
        }
        int qa3 = min(20, max(0, (__float2int_rd(t3) - 3) & ~3));
        float w3[12];
#pragma unroll
        for (int k = 0; k < 12; k++) {
            float d = t3 - (float)(qa3 + k);
            w3[k] = exp2f(CEXP * d * d);
        }
        float m0 = fmaxf(fmaxf(w3[0], w3[1]),  fmaxf(w3[2],  w3[3]));
        float m1 = fmaxf(fmaxf(w3[4], w3[5]),  fmaxf(w3[6],  w3[7]));
        float m2 = fmaxf(fmaxf(w3[8], w3[9]),  fmaxf(w3[10], w3[11]));
        float* base1 = base0 + 1024;
#pragma unroll
        for (int p = 0; p < 6; p++) {
            float wr = w2[p];
            float a  = wr * inv;
            float* row = base1 + (lo2 + p) * 32 + qa3;
            red4p(wr * m0, row,     a * w3[0], a * w3[1], a * w3[2],  a * w3[3]);
            red4p(wr * m1, row + 4, a * w3[4], a * w3[5], a * w3[6],  a * w3[7]);
            red4p(wr * m2, row + 8, a * w3[8], a * w3[9], a * w3[10], a * w3[11]);
        }
    }
}

// ---------------------------------------------------------------------------
extern "C" void kernel_launch(void* const* d_in, const int* in_sizes, int n_in,
                              void* d_out, int out_size) {
    const int*   seg  = (const int*)d_in[0];
    const int*   byx  = (const int*)d_in[1];
    const float* grad = (const float*)d_in[2];
    float*       out  = (float*)d_out;

    zero_kernel<<<512, 128>>>(out);                      // 512 x 16KB = 8MB
    count_kernel<<<(NPIX + 255) / 256, 256>>>(seg);
    hist_kernel<<<(NPIX + 255) / 256, 256>>>(seg, byx, grad, out);
}

// round 11
// speedup vs baseline: 1.6334x; 1.0099x over previous
#include <cuda_runtime.h>
#include <cstdint>

// Fixed problem shape
#define NPIX      102400            // B*H*W = 4*160*160
#define HW        25600             // H*W
#define NV        1024
#define OUT_ELEMS (NV * 2 * 32 * 32)   // 2,097,152 floats = 8 MB

// Gaussian in bin coordinates: t = (x+1)*16 - 0.5, sigma_bins = 0.8
// log2-space coefficient: -0.5/(0.8^2) * log2(e)
#define CEXP   (-1.12710546f)
#define SKIPTH (2e-5f)

// Self-restoring scratch: zero at module load; finalize_kernel returns it to
// zero after consuming it, so every kernel_launch call (and graph replay)
// starts from the same state. No zero kernel needed.
__device__ float g_scratch[OUT_ELEMS];
__device__ int   g_sizes[NV];

// ---------------------------------------------------------------------------
// Predicated vector reduction: issue red.v4 only if gate > SKIPTH.
// ---------------------------------------------------------------------------
__device__ __forceinline__ void red4p(float gate, float* p,
                                      float a, float b, float c, float d) {
    asm volatile(
        "{\n\t"
        ".reg .pred pg;\n\t"
        "setp.gt.f32 pg, %0, %1;\n\t"
        "@pg red.global.add.v4.f32 [%2], {%3,%4,%5,%6};\n\t"
        "}"
        :: "f"(gate), "f"(SKIPTH), "l"(p), "f"(a), "f"(b), "f"(c), "f"(d)
        : "memory");
}

__device__ __forceinline__ void red1i(int* p) {
    asm volatile("red.global.add.s32 [%0], 1;" :: "l"(p) : "memory");
}

// ---------------------------------------------------------------------------
// Kernel 1: windowed Parzen scatter into scratch + segment bincount.
// (R4 hist structure — measured 17.4us, at the REDG per-lane dispatch floor.)
// p-window 6 rows, q-window 12 cols 4-aligned, sub-threshold chunks
// predicated off. Normalization deferred to finalize.
// ---------------------------------------------------------------------------
__global__ void __launch_bounds__(256)
hist_kernel(const int* __restrict__ seg,
            const int* __restrict__ byx,
            const float* __restrict__ grad) {
    int n = blockIdx.x * blockDim.x + threadIdx.x;
    if (n >= NPIX) return;

    int v = seg[n];
    red1i(&g_sizes[v]);

    // bin coordinates: t = (x+1)*16 - 0.5
    float t0 = (float)byx[NPIX + n]     * 0.2f - 0.5f;
    float t1 = (float)byx[2 * NPIX + n] * 0.2f - 0.5f;
    int   b  = n / HW;
    int   hw = n - b * HW;
    float t2 = grad[b * 2 * HW + hw]      * 16.f + 15.5f;
    float t3 = grad[b * 2 * HW + HW + hw] * 16.f + 15.5f;

    float* base0 = g_scratch + (size_t)v * 2048;

    // ---- pair 0: dims (0,1) — always in range ----
    {
        int lo0 = min(26, max(0, __float2int_rd(t0) - 2));
        float w0[6];
#pragma unroll
        for (int k = 0; k < 6; k++) {
            float d = t0 - (float)(lo0 + k);
            w0[k] = exp2f(CEXP * d * d);
        }
        int qa1 = min(20, max(0, (__float2int_rd(t1) - 3) & ~3));
        float w1[12];
#pragma unroll
        for (int k = 0; k < 12; k++) {
            float d = t1 - (float)(qa1 + k);
            w1[k] = exp2f(CEXP * d * d);
        }
        float m0 = fmaxf(fmaxf(w1[0], w1[1]),  fmaxf(w1[2],  w1[3]));
        float m1 = fmaxf(fmaxf(w1[4], w1[5]),  fmaxf(w1[6],  w1[7]));
        float m2 = fmaxf(fmaxf(w1[8], w1[9]),  fmaxf(w1[10], w1[11]));
#pragma unroll
        for (int p = 0; p < 6; p++) {
            float a = w0[p];
            float* row = base0 + (lo0 + p) * 32 + qa1;
            red4p(a * m0, row,     a * w1[0], a * w1[1], a * w1[2],  a * w1[3]);
            red4p(a * m1, row + 4, a * w1[4], a * w1[5], a * w1[6],  a * w1[7]);
            red4p(a * m2, row + 8, a * w1[8], a * w1[9], a * w1[10], a * w1[11]);
        }
    }

    // ---- pair 1: dims (2,3) — grads can fall outside all bins -> skip ----
    if (t2 > -3.5f && t2 < 34.5f && t3 > -3.5f && t3 < 34.5f) {
        int lo2 = min(26, max(0, __float2int_rd(t2) - 2));
        float w2[6];
#pragma unroll
        for (int k = 0; k < 6; k++) {
            float d = t2 - (float)(lo2 + k);
            w2[k] = exp2f(CEXP * d * d);
        }
        int qa3 = min(20, max(0, (__float2int_rd(t3) - 3) & ~3));
        float w3[12];
#pragma unroll
        for (int k = 0; k < 12; k++) {
            float d = t3 - (float)(qa3 + k);
            w3[k] = exp2f(CEXP * d * d);
        }
        float m0 = fmaxf(fmaxf(w3[0], w3[1]),  fmaxf(w3[2],  w3[3]));
        float m1 = fmaxf(fmaxf(w3[4], w3[5]),  fmaxf(w3[6],  w3[7]));
        float m2 = fmaxf(fmaxf(w3[8], w3[9]),  fmaxf(w3[10], w3[11]));
        float* base1 = base0 + 1024;
#pragma unroll
        for (int p = 0; p < 6; p++) {
            float a = w2[p];
            float* row = base1 + (lo2 + p) * 32 + qa3;
            red4p(a * m0, row,     a * w3[0], a * w3[1], a * w3[2],  a * w3[3]);
            red4p(a * m1, row + 4, a * w3[4], a * w3[5], a * w3[6],  a * w3[7]);
            red4p(a * m2, row + 8, a * w3[8], a * w3[9], a * w3[10], a * w3[11]);
        }
    }
}

// ---------------------------------------------------------------------------
// Kernel 2: finalize — one block per segment.
// out[v,:] = scratch[v,:] / size[v]; then restore scratch[v,:]=0 and
// g_sizes[v]=0 for the next call. Only this block touches segment v's
// counter/scratch, so the restore has no cross-block ordering hazard.
// ---------------------------------------------------------------------------
__global__ void __launch_bounds__(512)
finalize_kernel(float4* __restrict__ out) {
    __shared__ float s_inv;
    int v = blockIdx.x;
    if (threadIdx.x == 0) {
        int sz = g_sizes[v];
        s_inv = sz ? 1.0f / (float)sz : 0.0f;   // den = sizes*(P/32)^2 = sizes
        g_sizes[v] = 0;                          // restore for next call
    }
    __syncthreads();
    float inv = s_inv;

    float4* src = reinterpret_cast<float4*>(g_scratch) + (size_t)v * 512;
    float4* dst = out + (size_t)v * 512;
    int i = threadIdx.x;                         // 512 threads x 1 float4
    float4 x = src[i];
    x.x *= inv; x.y *= inv; x.z *= inv; x.w *= inv;
    dst[i] = x;
    src[i] = make_float4(0.f, 0.f, 0.f, 0.f);    // restore scratch
}

// ---------------------------------------------------------------------------
extern "C" void kernel_launch(void* const* d_in, const int* in_sizes, int n_in,
                              void* d_out, int out_size) {
    const int*   seg  = (const int*)d_in[0];
    const int*   byx  = (const int*)d_in[1];
    const float* grad = (const float*)d_in[2];
    float4*      out  = (float4*)d_out;

    hist_kernel<<<(NPIX + 255) / 256, 256>>>(seg, byx, grad);
    finalize_kernel<<<NV, 512>>>(out);
}